// round 4
// baseline (speedup 1.0000x reference)
#include <cuda_runtime.h>
#include <math.h>

#define Nn 50000
#define Ee 600000
#define Hh 128
#define Cc 40

// ---------------- scratch (static device globals; no allocation) ----------------
__device__ int   g_deg[Nn];
__device__ int   g_row_ptr[Nn + 1];
__device__ int   g_cursor[Nn];
__device__ int   g_col[Ee];
__device__ float g_inv_deg[Nn];
__device__ int   g_bsums[64];
__device__ int   g_is64;
__device__ float g_agg[(size_t)Nn * Hh];
__device__ float g_h1[(size_t)Nn * Hh];
__device__ float g_h2[(size_t)Nn * Hh];

// buffer selectors: 0 = g_agg, 1 = g_h1, 2 = g_h2, 3 = external x
__device__ __forceinline__ const float* rd_buf(int sel, const float* x) {
    switch (sel) {
        case 0: return g_agg;
        case 1: return g_h1;
        case 2: return g_h2;
        default: return x;
    }
}
__device__ __forceinline__ float* wr_buf(int sel) {
    switch (sel) {
        case 0: return g_agg;
        case 1: return g_h1;
        default: return g_h2;
    }
}

// edge_index element read that works for both int32 and int64 storage
__device__ __forceinline__ int edge_at(const void* ei, int is64, long long idx) {
    if (is64) return (int)((const long long*)ei)[idx];
    return ((const int*)ei)[idx];
}

// ---------------- dtype detection (1 thread) ----------------
__global__ void detect_dtype_kernel(const void* __restrict__ ei) {
    if (threadIdx.x == 0 && blockIdx.x == 0) {
        const long long* p64 = (const long long*)ei;
        int ok64 = 1;
        for (int i = 0; i < 64; i++) {
            long long v = p64[i];
            if (v < 0 || v >= Nn) { ok64 = 0; break; }
        }
        g_is64 = ok64;
    }
}

// ---------------- CSR build ----------------
__global__ void zero_deg_kernel() {
    int i = blockIdx.x * blockDim.x + threadIdx.x;
    if (i < Nn) g_deg[i] = 0;
}

__global__ void count_deg_kernel(const void* __restrict__ ei) {
    int e = blockIdx.x * blockDim.x + threadIdx.x;
    if (e < Ee) {
        int dst = edge_at(ei, g_is64, (long long)Ee + e);
        atomicAdd(&g_deg[dst], 1);
    }
}

// inclusive scan within blocks of 1024; block totals to g_bsums
__global__ void scan_blocks_kernel() {
    __shared__ int s[1024];
    int t = threadIdx.x;
    int i = blockIdx.x * 1024 + t;
    int v = (i < Nn) ? g_deg[i] : 0;
    s[t] = v;
    __syncthreads();
    for (int off = 1; off < 1024; off <<= 1) {
        int add = (t >= off) ? s[t - off] : 0;
        __syncthreads();
        s[t] += add;
        __syncthreads();
    }
    if (i < Nn) g_row_ptr[i + 1] = s[t];   // staged inclusive (pre-offset)
    if (t == 1023) g_bsums[blockIdx.x] = s[1023];
}

__global__ void scan_sums_kernel(int nb) {
    if (threadIdx.x == 0 && blockIdx.x == 0) {
        int acc = 0;
        for (int i = 0; i < nb; i++) { int tt = g_bsums[i]; g_bsums[i] = acc; acc += tt; }
    }
}

__global__ void scan_finalize_kernel() {
    int i = blockIdx.x * 1024 + threadIdx.x;
    if (i < Nn) {
        int incl = g_row_ptr[i + 1] + g_bsums[blockIdx.x];
        g_row_ptr[i + 1] = incl;
        int d = g_deg[i];
        g_cursor[i] = incl - d;            // exclusive start
        g_inv_deg[i] = 1.0f / (float)(d > 1 ? d : 1);
        if (i == 0) g_row_ptr[0] = 0;
    }
}

__global__ void fill_csr_kernel(const void* __restrict__ ei) {
    int e = blockIdx.x * blockDim.x + threadIdx.x;
    if (e < Ee) {
        int is64 = g_is64;
        int dst = edge_at(ei, is64, (long long)Ee + e);
        int src = edge_at(ei, is64, e);
        int pos = atomicAdd(&g_cursor[dst], 1);
        g_col[pos] = src;
    }
}

// ---------------- mean aggregation: one warp per node ----------------
__global__ __launch_bounds__(256) void aggregate_kernel(int selIn, const float* __restrict__ x) {
    const float* in = rd_buf(selIn, x);
    int warp = (blockIdx.x * blockDim.x + threadIdx.x) >> 5;
    if (warp >= Nn) return;
    int lane = threadIdx.x & 31;
    int s = g_row_ptr[warp];
    int e = g_row_ptr[warp + 1];
    float4 acc = make_float4(0.f, 0.f, 0.f, 0.f);
    for (int i = s; i < e; i++) {
        int nbr = g_col[i];
        float4 v = *(const float4*)(in + (size_t)nbr * Hh + lane * 4);
        acc.x += v.x; acc.y += v.y; acc.z += v.z; acc.w += v.w;
    }
    float id = g_inv_deg[warp];
    acc.x *= id; acc.y *= id; acc.z *= id; acc.w *= id;
    *(float4*)(g_agg + (size_t)warp * Hh + lane * 4) = acc;
}

// ---------------- fused dual GEMM: C = relu(A1@W1 + A2@W2 + b) ----------------
// BM=128, BN=128, BK=8; 256 threads, 8x8 per thread. selA2 < 0 -> single GEMM.
__global__ __launch_bounds__(256) void gemm_dual_kernel(
    int selA1, const float* __restrict__ W1,
    int selA2, const float* __restrict__ W2,
    const float* __restrict__ bias, int selC,
    const float* __restrict__ x, int M)
{
    const float* A1 = rd_buf(selA1, x);
    const float* A2 = (selA2 < 0) ? nullptr : rd_buf(selA2, x);
    float* C = wr_buf(selC);

    __shared__ float As[8][132];
    __shared__ float Bs[8][128];
    const int tx = threadIdx.x;
    const int tr = tx >> 4;          // 0..15 -> rows tr*8..tr*8+7
    const int tc = tx & 15;          // 0..15 -> cols tc*8..tc*8+7
    const int block_row = blockIdx.x * 128;

    float acc[8][8];
#pragma unroll
    for (int i = 0; i < 8; i++)
#pragma unroll
        for (int j = 0; j < 8; j++) acc[i][j] = 0.f;

    const int nK = (selA2 >= 0) ? 256 : 128;
    for (int k0 = 0; k0 < nK; k0 += 8) {
        const float* A = (k0 < 128) ? A1 : A2;
        const float* W = (k0 < 128) ? W1 : W2;
        const int kk = k0 & 127;
#pragma unroll
        for (int i = 0; i < 4; i++) {
            int idx = tx + i * 256;
            int r = idx >> 3, c = idx & 7;
            int gr = block_row + r;
            As[c][r] = (gr < M) ? A[(size_t)gr * 128 + kk + c] : 0.f;
        }
#pragma unroll
        for (int i = 0; i < 4; i++) {
            int idx = tx + i * 256;
            int r = idx >> 7, c = idx & 127;
            Bs[r][c] = W[(size_t)(kk + r) * 128 + c];
        }
        __syncthreads();
#pragma unroll
        for (int k = 0; k < 8; k++) {
            float a[8], b[8];
#pragma unroll
            for (int i = 0; i < 8; i++) a[i] = As[k][tr * 8 + i];
#pragma unroll
            for (int j = 0; j < 8; j++) b[j] = Bs[k][tc * 8 + j];
#pragma unroll
            for (int i = 0; i < 8; i++)
#pragma unroll
                for (int j = 0; j < 8; j++)
                    acc[i][j] += a[i] * b[j];
        }
        __syncthreads();
    }
#pragma unroll
    for (int i = 0; i < 8; i++) {
        int gr = block_row + tr * 8 + i;
        if (gr < M) {
#pragma unroll
            for (int j = 0; j < 8; j++) {
                float v = acc[i][j] + bias[tc * 8 + j];
                C[(size_t)gr * 128 + tc * 8 + j] = fmaxf(v, 0.f);
            }
        }
    }
}

// ---------------- fused lin2 + log_softmax: 32 rows per block ----------------
// reads h from g_h2 directly
__global__ __launch_bounds__(320) void lin2_logsoftmax_kernel(
    const float* __restrict__ W, const float* __restrict__ b,
    float* __restrict__ outp, int M)
{
    __shared__ float Ws[128 * 40];      // 20 KB, layout [k][j]
    __shared__ float bs[40];
    __shared__ float hs[32][128];       // 16 KB
    __shared__ float logits[32][40];
    __shared__ float rmax[32], rlse[32];

    const int t = threadIdx.x;
    for (int i = t; i < 128 * 40; i += 320) Ws[i] = W[i];
    if (t < 40) bs[t] = b[t];

    const int row0 = blockIdx.x * 32;
    for (int i = t; i < 32 * 128; i += 320) {
        int r = i >> 7, c = i & 127;
        int gr = row0 + r;
        hs[r][c] = (gr < M) ? g_h2[(size_t)gr * 128 + c] : 0.f;
    }
    __syncthreads();

    const int j = t % 40;
    const int r0 = t / 40;              // 0..7
    float acc[4];
#pragma unroll
    for (int rr = 0; rr < 4; rr++) acc[rr] = bs[j];
#pragma unroll
    for (int k = 0; k < 128; k++) {
        float w = Ws[k * 40 + j];
#pragma unroll
        for (int rr = 0; rr < 4; rr++)
            acc[rr] += hs[r0 + rr * 8][k] * w;
    }
#pragma unroll
    for (int rr = 0; rr < 4; rr++)
        logits[r0 + rr * 8][j] = acc[rr];
    __syncthreads();

    if (t < 32) {
        float m = -1e30f;
#pragma unroll
        for (int jj = 0; jj < 40; jj++) m = fmaxf(m, logits[t][jj]);
        float s = 0.f;
#pragma unroll
        for (int jj = 0; jj < 40; jj++) s += expf(logits[t][jj] - m);
        rmax[t] = m;
        rlse[t] = logf(s);
    }
    __syncthreads();

#pragma unroll
    for (int rr = 0; rr < 4; rr++) {
        int r = r0 + rr * 8;
        int gr = row0 + r;
        if (gr < M)
            outp[(size_t)gr * 40 + j] = logits[r][j] - rmax[r] - rlse[r];
    }
}

// ---------------- launcher ----------------
extern "C" void kernel_launch(void* const* d_in, const int* in_sizes, int n_in,
                              void* d_out, int out_size) {
    const float* x  = (const float*)d_in[0];
    const void*  ei = d_in[1];
    const float *Wl1 = (const float*)d_in[2],  *bl1 = (const float*)d_in[3],  *Wr1 = (const float*)d_in[4];
    const float *Wl2 = (const float*)d_in[5],  *bl2 = (const float*)d_in[6],  *Wr2 = (const float*)d_in[7];
    const float *Wl3 = (const float*)d_in[8],  *bl3 = (const float*)d_in[9],  *Wr3 = (const float*)d_in[10];
    const float *Wlin1 = (const float*)d_in[11], *blin1 = (const float*)d_in[12];
    const float *Wlin2 = (const float*)d_in[13], *blin2 = (const float*)d_in[14];
    float* outp = (float*)d_out;

    const int TB = 256;
    const int edge_blocks = (Ee + TB - 1) / TB;
    const int node_blocks_1024 = (Nn + 1023) / 1024;
    const int agg_blocks = (Nn * 32 + TB - 1) / TB;   // one warp per node
    const int gemm_blocks = (Nn + 127) / 128;
    const int sm_blocks = (Nn + 31) / 32;

    // ---- CSR build (once per launch, reused by 3 layers) ----
    detect_dtype_kernel<<<1, 32>>>(ei);
    zero_deg_kernel<<<node_blocks_1024 * 4, TB>>>();
    count_deg_kernel<<<edge_blocks, TB>>>(ei);
    scan_blocks_kernel<<<node_blocks_1024, 1024>>>();
    scan_sums_kernel<<<1, 32>>>(node_blocks_1024);
    scan_finalize_kernel<<<node_blocks_1024, 1024>>>();
    fill_csr_kernel<<<edge_blocks, TB>>>(ei);

    // selectors: 0 = g_agg, 1 = g_h1, 2 = g_h2, 3 = x
    // ---- layer 1: agg(x) -> g_agg; h1 = relu(agg@Wl1 + x@Wr1 + b) ----
    aggregate_kernel<<<agg_blocks, TB>>>(3, x);
    gemm_dual_kernel<<<gemm_blocks, 256>>>(0, Wl1, 3, Wr1, bl1, 1, x, Nn);
    // ---- layer 2 ----
    aggregate_kernel<<<agg_blocks, TB>>>(1, x);
    gemm_dual_kernel<<<gemm_blocks, 256>>>(0, Wl2, 1, Wr2, bl2, 2, x, Nn);
    // ---- layer 3 ----
    aggregate_kernel<<<agg_blocks, TB>>>(2, x);
    gemm_dual_kernel<<<gemm_blocks, 256>>>(0, Wl3, 2, Wr3, bl3, 1, x, Nn);
    // ---- lin1 + relu: h2 = relu(h1 @ W_lin1 + b) ----
    gemm_dual_kernel<<<gemm_blocks, 256>>>(1, Wlin1, -1, nullptr, blin1, 2, x, Nn);
    // ---- lin2 + log_softmax (reads g_h2) ----
    lin2_logsoftmax_kernel<<<sm_blocks, 320>>>(Wlin2, blin2, outp, Nn);
}

// round 5
// speedup vs baseline: 2.2914x; 2.2914x over previous
#include <cuda_runtime.h>
#include <math.h>
#include <stdint.h>

#define Nn 50000
#define Ee 600000
#define Hh 128
#define Cc 40

// ---------------- scratch (static device globals; no allocation) ----------------
__device__ int   g_deg[Nn];
__device__ int   g_row_ptr[Nn + 1];
__device__ int   g_cursor[Nn];
__device__ int   g_col[Ee];
__device__ float g_inv_deg[Nn];
__device__ int   g_bsums[64];
__device__ int   g_is64;
__device__ float g_agg[(size_t)Nn * Hh];
__device__ float g_h1[(size_t)Nn * Hh];
__device__ float g_h2[(size_t)Nn * Hh];

// buffer selectors: 0 = g_agg, 1 = g_h1, 2 = g_h2, 3 = external x
__device__ __forceinline__ const float* rd_buf(int sel, const float* x) {
    switch (sel) {
        case 0: return g_agg;
        case 1: return g_h1;
        case 2: return g_h2;
        default: return x;
    }
}
__device__ __forceinline__ float* wr_buf(int sel) {
    switch (sel) {
        case 0: return g_agg;
        case 1: return g_h1;
        default: return g_h2;
    }
}

// edge_index element read that works for both int32 and int64 storage
__device__ __forceinline__ int edge_at(const void* ei, int is64, long long idx) {
    if (is64) return (int)((const long long*)ei)[idx];
    return ((const int*)ei)[idx];
}

// ---------------- dtype detection (1 thread) ----------------
__global__ void detect_dtype_kernel(const void* __restrict__ ei) {
    if (threadIdx.x == 0 && blockIdx.x == 0) {
        const long long* p64 = (const long long*)ei;
        int ok64 = 1;
        for (int i = 0; i < 64; i++) {
            long long v = p64[i];
            if (v < 0 || v >= Nn) { ok64 = 0; break; }
        }
        g_is64 = ok64;
    }
}

// ---------------- CSR build ----------------
__global__ void zero_deg_kernel() {
    int i = blockIdx.x * blockDim.x + threadIdx.x;
    if (i < Nn) g_deg[i] = 0;
}

__global__ void count_deg_kernel(const void* __restrict__ ei) {
    int e = blockIdx.x * blockDim.x + threadIdx.x;
    if (e < Ee) {
        int dst = edge_at(ei, g_is64, (long long)Ee + e);
        atomicAdd(&g_deg[dst], 1);
    }
}

__global__ void scan_blocks_kernel() {
    __shared__ int s[1024];
    int t = threadIdx.x;
    int i = blockIdx.x * 1024 + t;
    int v = (i < Nn) ? g_deg[i] : 0;
    s[t] = v;
    __syncthreads();
    for (int off = 1; off < 1024; off <<= 1) {
        int add = (t >= off) ? s[t - off] : 0;
        __syncthreads();
        s[t] += add;
        __syncthreads();
    }
    if (i < Nn) g_row_ptr[i + 1] = s[t];
    if (t == 1023) g_bsums[blockIdx.x] = s[1023];
}

__global__ void scan_sums_kernel(int nb) {
    if (threadIdx.x == 0 && blockIdx.x == 0) {
        int acc = 0;
        for (int i = 0; i < nb; i++) { int tt = g_bsums[i]; g_bsums[i] = acc; acc += tt; }
    }
}

__global__ void scan_finalize_kernel() {
    int i = blockIdx.x * 1024 + threadIdx.x;
    if (i < Nn) {
        int incl = g_row_ptr[i + 1] + g_bsums[blockIdx.x];
        g_row_ptr[i + 1] = incl;
        int d = g_deg[i];
        g_cursor[i] = incl - d;
        g_inv_deg[i] = 1.0f / (float)(d > 1 ? d : 1);
        if (i == 0) g_row_ptr[0] = 0;
    }
}

__global__ void fill_csr_kernel(const void* __restrict__ ei) {
    int e = blockIdx.x * blockDim.x + threadIdx.x;
    if (e < Ee) {
        int is64 = g_is64;
        int dst = edge_at(ei, is64, (long long)Ee + e);
        int src = edge_at(ei, is64, e);
        int pos = atomicAdd(&g_cursor[dst], 1);
        g_col[pos] = src;
    }
}

// ---------------- mean aggregation: one warp per node ----------------
__global__ __launch_bounds__(256) void aggregate_kernel(int selIn, const float* __restrict__ x) {
    const float* in = rd_buf(selIn, x);
    int warp = (blockIdx.x * blockDim.x + threadIdx.x) >> 5;
    if (warp >= Nn) return;
    int lane = threadIdx.x & 31;
    int s = g_row_ptr[warp];
    int e = g_row_ptr[warp + 1];
    float4 acc = make_float4(0.f, 0.f, 0.f, 0.f);
    for (int i = s; i < e; i++) {
        int nbr = g_col[i];
        float4 v = *(const float4*)(in + (size_t)nbr * Hh + lane * 4);
        acc.x += v.x; acc.y += v.y; acc.z += v.z; acc.w += v.w;
    }
    float id = g_inv_deg[warp];
    acc.x *= id; acc.y *= id; acc.z *= id; acc.w *= id;
    *(float4*)(g_agg + (size_t)warp * Hh + lane * 4) = acc;
}

// ---------------- tf32 tensor-core dual GEMM ----------------
// C = relu(A1@W1 [+ A2@W2] + b), A: [M,128] each, W: [128,128], C: [M,128]
// BM=128, BN=128, BK=16; 256 threads = 8 warps (4 x 2), warp tile 32x64.
__device__ __forceinline__ uint32_t f2tf32(float x) {
    uint32_t u;
    asm("cvt.rna.tf32.f32 %0, %1;" : "=r"(u) : "f"(x));
    return u;
}

__global__ __launch_bounds__(256) void gemm_tf32_kernel(
    int selA1, const float* __restrict__ W1,
    int selA2, const float* __restrict__ W2,
    const float* __restrict__ bias, int selC,
    const float* __restrict__ x, int M)
{
    const float* A1 = rd_buf(selA1, x);
    const float* A2 = (selA2 < 0) ? A1 : rd_buf(selA2, x);
    float* C = wr_buf(selC);

    __shared__ float As[2][128][20];   // [stage][row][k], stride 20 -> conflict-free frags
    __shared__ float Bs[2][16][128];   // [stage][k][n], col XOR-swizzled by (k&3)<<3

    const int t = threadIdx.x;
    const int lane = t & 31;
    const int warp = t >> 5;
    const int g = lane >> 2;       // groupID 0..7
    const int tig = lane & 3;      // threadID_in_group 0..3
    const int warpM = warp & 3;    // 4 warps over M
    const int warpN = warp >> 2;   // 2 warps over N
    const int block_row = blockIdx.x * 128;

    const int nIter = (selA2 >= 0) ? 16 : 8;   // K=256 or K=128 in BK=16 steps

    float acc[2][8][4];
#pragma unroll
    for (int mt = 0; mt < 2; mt++)
#pragma unroll
        for (int nt = 0; nt < 8; nt++)
#pragma unroll
            for (int i = 0; i < 4; i++) acc[mt][nt][i] = 0.f;

    uint32_t asA = (uint32_t)__cvta_generic_to_shared(&As[0][0][0]);
    uint32_t asB = (uint32_t)__cvta_generic_to_shared(&Bs[0][0][0]);

    // -------- async stage loader --------
    auto issue = [&](int it, int s) {
        const float* Ap = (it < 8) ? A1 : A2;
        const float* Wp = (it < 8) ? W1 : W2;
        const int kk = (it & 7) * 16;
        // A tile: 128 rows x 16 k = 512 float4; 2 per thread
#pragma unroll
        for (int i = 0; i < 2; i++) {
            int idx = t + i * 256;
            int r = idx >> 2;
            int c4 = (idx & 3) * 4;
            int gr = block_row + r;
            int grc = (gr < M) ? gr : (M - 1);
            const float* src = Ap + (size_t)grc * 128 + kk + c4;
            uint32_t dst = asA + (uint32_t)(((s * 128 + r) * 20 + c4) * 4);
            int sz = (gr < M) ? 16 : 0;
            asm volatile("cp.async.cg.shared.global [%0], [%1], 16, %2;"
                         :: "r"(dst), "l"(src), "r"(sz));
        }
        // B tile: 16 k x 128 n = 512 float4; 2 per thread, swizzled column
#pragma unroll
        for (int i = 0; i < 2; i++) {
            int idx = t + i * 256;
            int kr = idx >> 5;
            int n = (idx & 31) * 4;
            const float* src = Wp + (size_t)(kk + kr) * 128 + n;
            int pc = n ^ ((kr & 3) << 3);
            uint32_t dst = asB + (uint32_t)(((s * 16 + kr) * 128 + pc) * 4);
            asm volatile("cp.async.cg.shared.global [%0], [%1], 16;"
                         :: "r"(dst), "l"(src));
        }
        asm volatile("cp.async.commit_group;");
    };

    issue(0, 0);

    for (int it = 0; it < nIter; it++) {
        const int s = it & 1;
        if (it + 1 < nIter) {
            issue(it + 1, (it + 1) & 1);
            asm volatile("cp.async.wait_group 1;");
        } else {
            asm volatile("cp.async.wait_group 0;");
        }
        __syncthreads();

#pragma unroll
        for (int ks = 0; ks < 2; ks++) {
            const int kc = ks * 8 + tig;
            uint32_t af[2][4];
#pragma unroll
            for (int mt = 0; mt < 2; mt++) {
                int rb = warpM * 32 + mt * 16;
                af[mt][0] = f2tf32(As[s][rb + g][kc]);
                af[mt][1] = f2tf32(As[s][rb + g + 8][kc]);
                af[mt][2] = f2tf32(As[s][rb + g][kc + 4]);
                af[mt][3] = f2tf32(As[s][rb + g + 8][kc + 4]);
            }
            uint32_t bf[8][2];
            const int sw = (tig & 3) << 3;
#pragma unroll
            for (int nt = 0; nt < 8; nt++) {
                int nb = warpN * 64 + nt * 8 + g;
                bf[nt][0] = f2tf32(Bs[s][kc][nb ^ sw]);
                bf[nt][1] = f2tf32(Bs[s][kc + 4][nb ^ sw]);
            }
#pragma unroll
            for (int mt = 0; mt < 2; mt++)
#pragma unroll
                for (int nt = 0; nt < 8; nt++) {
                    asm volatile(
                        "mma.sync.aligned.m16n8k8.row.col.f32.tf32.tf32.f32 "
                        "{%0,%1,%2,%3}, {%4,%5,%6,%7}, {%8,%9}, {%0,%1,%2,%3};"
                        : "+f"(acc[mt][nt][0]), "+f"(acc[mt][nt][1]),
                          "+f"(acc[mt][nt][2]), "+f"(acc[mt][nt][3])
                        : "r"(af[mt][0]), "r"(af[mt][1]), "r"(af[mt][2]), "r"(af[mt][3]),
                          "r"(bf[nt][0]), "r"(bf[nt][1]));
                }
        }
        __syncthreads();
    }

    // -------- epilogue: bias + relu, float2 stores --------
#pragma unroll
    for (int mt = 0; mt < 2; mt++) {
        int r0 = block_row + warpM * 32 + mt * 16 + g;
        int r1 = r0 + 8;
#pragma unroll
        for (int nt = 0; nt < 8; nt++) {
            int c0 = warpN * 64 + nt * 8 + 2 * tig;
            float2 bv = *(const float2*)(bias + c0);
            if (r0 < M) {
                float2 o;
                o.x = fmaxf(acc[mt][nt][0] + bv.x, 0.f);
                o.y = fmaxf(acc[mt][nt][1] + bv.y, 0.f);
                *(float2*)(C + (size_t)r0 * 128 + c0) = o;
            }
            if (r1 < M) {
                float2 o;
                o.x = fmaxf(acc[mt][nt][2] + bv.x, 0.f);
                o.y = fmaxf(acc[mt][nt][3] + bv.y, 0.f);
                *(float2*)(C + (size_t)r1 * 128 + c0) = o;
            }
        }
    }
}

// ---------------- fused lin2 + log_softmax: 32 rows per block ----------------
__global__ __launch_bounds__(320) void lin2_logsoftmax_kernel(
    const float* __restrict__ W, const float* __restrict__ b,
    float* __restrict__ outp, int M)
{
    __shared__ float Ws[128 * 40];
    __shared__ float bs[40];
    __shared__ float hs[32][128];
    __shared__ float logits[32][40];
    __shared__ float rmax[32], rlse[32];

    const int t = threadIdx.x;
    for (int i = t; i < 128 * 40; i += 320) Ws[i] = W[i];
    if (t < 40) bs[t] = b[t];

    const int row0 = blockIdx.x * 32;
    for (int i = t; i < 32 * 128; i += 320) {
        int r = i >> 7, c = i & 127;
        int gr = row0 + r;
        hs[r][c] = (gr < M) ? g_h2[(size_t)gr * 128 + c] : 0.f;
    }
    __syncthreads();

    const int j = t % 40;
    const int r0 = t / 40;
    float acc[4];
#pragma unroll
    for (int rr = 0; rr < 4; rr++) acc[rr] = bs[j];
#pragma unroll
    for (int k = 0; k < 128; k++) {
        float w = Ws[k * 40 + j];
#pragma unroll
        for (int rr = 0; rr < 4; rr++)
            acc[rr] += hs[r0 + rr * 8][k] * w;
    }
#pragma unroll
    for (int rr = 0; rr < 4; rr++)
        logits[r0 + rr * 8][j] = acc[rr];
    __syncthreads();

    if (t < 32) {
        float m = -1e30f;
#pragma unroll
        for (int jj = 0; jj < 40; jj++) m = fmaxf(m, logits[t][jj]);
        float s = 0.f;
#pragma unroll
        for (int jj = 0; jj < 40; jj++) s += expf(logits[t][jj] - m);
        rmax[t] = m;
        rlse[t] = logf(s);
    }
    __syncthreads();

#pragma unroll
    for (int rr = 0; rr < 4; rr++) {
        int r = r0 + rr * 8;
        int gr = row0 + r;
        if (gr < M)
            outp[(size_t)gr * 40 + j] = logits[r][j] - rmax[r] - rlse[r];
    }
}

// ---------------- launcher ----------------
extern "C" void kernel_launch(void* const* d_in, const int* in_sizes, int n_in,
                              void* d_out, int out_size) {
    const float* x  = (const float*)d_in[0];
    const void*  ei = d_in[1];
    const float *Wl1 = (const float*)d_in[2],  *bl1 = (const float*)d_in[3],  *Wr1 = (const float*)d_in[4];
    const float *Wl2 = (const float*)d_in[5],  *bl2 = (const float*)d_in[6],  *Wr2 = (const float*)d_in[7];
    const float *Wl3 = (const float*)d_in[8],  *bl3 = (const float*)d_in[9],  *Wr3 = (const float*)d_in[10];
    const float *Wlin1 = (const float*)d_in[11], *blin1 = (const float*)d_in[12];
    const float *Wlin2 = (const float*)d_in[13], *blin2 = (const float*)d_in[14];
    float* outp = (float*)d_out;

    const int TB = 256;
    const int edge_blocks = (Ee + TB - 1) / TB;
    const int node_blocks_1024 = (Nn + 1023) / 1024;
    const int agg_blocks = (Nn * 32 + TB - 1) / TB;
    const int gemm_blocks = (Nn + 127) / 128;
    const int sm_blocks = (Nn + 31) / 32;

    // ---- CSR build ----
    detect_dtype_kernel<<<1, 32>>>(ei);
    zero_deg_kernel<<<node_blocks_1024 * 4, TB>>>();
    count_deg_kernel<<<edge_blocks, TB>>>(ei);
    scan_blocks_kernel<<<node_blocks_1024, 1024>>>();
    scan_sums_kernel<<<1, 32>>>(node_blocks_1024);
    scan_finalize_kernel<<<node_blocks_1024, 1024>>>();
    fill_csr_kernel<<<edge_blocks, TB>>>(ei);

    // selectors: 0 = g_agg, 1 = g_h1, 2 = g_h2, 3 = x
    // ---- layer 1 ----
    aggregate_kernel<<<agg_blocks, TB>>>(3, x);
    gemm_tf32_kernel<<<gemm_blocks, 256>>>(0, Wl1, 3, Wr1, bl1, 1, x, Nn);
    // ---- layer 2 ----
    aggregate_kernel<<<agg_blocks, TB>>>(1, x);
    gemm_tf32_kernel<<<gemm_blocks, 256>>>(0, Wl2, 1, Wr2, bl2, 2, x, Nn);
    // ---- layer 3 ----
    aggregate_kernel<<<agg_blocks, TB>>>(2, x);
    gemm_tf32_kernel<<<gemm_blocks, 256>>>(0, Wl3, 2, Wr3, bl3, 1, x, Nn);
    // ---- lin1 + relu ----
    gemm_tf32_kernel<<<gemm_blocks, 256>>>(1, Wlin1, -1, nullptr, blin1, 2, x, Nn);
    // ---- lin2 + log_softmax ----
    lin2_logsoftmax_kernel<<<sm_blocks, 320>>>(Wlin2, blin2, outp, Nn);
}

// round 9
// speedup vs baseline: 2.3236x; 1.0141x over previous
#include <cuda_runtime.h>
#include <math.h>
#include <stdint.h>

#define Nn 50000
#define Ee 600000
#define Hh 128
#define Cc 40

// ---------------- scratch (static device globals; no allocation) ----------------
__device__ int   g_deg[Nn];
__device__ int   g_row_ptr[Nn + 1];
__device__ int   g_cursor[Nn];
__device__ int   g_col[Ee];
__device__ float g_inv_deg[Nn];
__device__ int   g_bsums[64];
__device__ int   g_is64;
__device__ float g_agg[(size_t)Nn * Hh];
__device__ float g_h1[(size_t)Nn * Hh];
__device__ float g_h2[(size_t)Nn * Hh];

// buffer selectors: 0 = g_agg, 1 = g_h1, 2 = g_h2, 3 = external x
__device__ __forceinline__ const float* rd_buf(int sel, const float* x) {
    switch (sel) {
        case 0: return g_agg;
        case 1: return g_h1;
        case 2: return g_h2;
        default: return x;
    }
}
__device__ __forceinline__ float* wr_buf(int sel) {
    switch (sel) {
        case 0: return g_agg;
        case 1: return g_h1;
        default: return g_h2;
    }
}

__device__ __forceinline__ int edge_at(const void* ei, int is64, long long idx) {
    if (is64) return (int)((const long long*)ei)[idx];
    return ((const int*)ei)[idx];
}

// ---------------- dtype detection (1 thread) ----------------
__global__ void detect_dtype_kernel(const void* __restrict__ ei) {
    if (threadIdx.x == 0 && blockIdx.x == 0) {
        const long long* p64 = (const long long*)ei;
        int ok64 = 1;
        for (int i = 0; i < 64; i++) {
            long long v = p64[i];
            if (v < 0 || v >= Nn) { ok64 = 0; break; }
        }
        g_is64 = ok64;
    }
}

// ---------------- CSR build ----------------
__global__ void zero_deg_kernel() {
    int i = blockIdx.x * blockDim.x + threadIdx.x;
    if (i < Nn) g_deg[i] = 0;
}

__global__ void count_deg_kernel(const void* __restrict__ ei) {
    int e = blockIdx.x * blockDim.x + threadIdx.x;
    if (e < Ee) {
        int dst = edge_at(ei, g_is64, (long long)Ee + e);
        atomicAdd(&g_deg[dst], 1);
    }
}

__global__ void scan_blocks_kernel() {
    __shared__ int s[1024];
    int t = threadIdx.x;
    int i = blockIdx.x * 1024 + t;
    int v = (i < Nn) ? g_deg[i] : 0;
    s[t] = v;
    __syncthreads();
    for (int off = 1; off < 1024; off <<= 1) {
        int add = (t >= off) ? s[t - off] : 0;
        __syncthreads();
        s[t] += add;
        __syncthreads();
    }
    if (i < Nn) g_row_ptr[i + 1] = s[t];
    if (t == 1023) g_bsums[blockIdx.x] = s[1023];
}

__global__ void scan_sums_kernel(int nb) {
    if (threadIdx.x == 0 && blockIdx.x == 0) {
        int acc = 0;
        for (int i = 0; i < nb; i++) { int tt = g_bsums[i]; g_bsums[i] = acc; acc += tt; }
    }
}

__global__ void scan_finalize_kernel() {
    int i = blockIdx.x * 1024 + threadIdx.x;
    if (i < Nn) {
        int incl = g_row_ptr[i + 1] + g_bsums[blockIdx.x];
        g_row_ptr[i + 1] = incl;
        int d = g_deg[i];
        g_cursor[i] = incl - d;
        g_inv_deg[i] = 1.0f / (float)(d > 1 ? d : 1);
        if (i == 0) g_row_ptr[0] = 0;
    }
}

__global__ void fill_csr_kernel(const void* __restrict__ ei) {
    int e = blockIdx.x * blockDim.x + threadIdx.x;
    if (e < Ee) {
        int is64 = g_is64;
        int dst = edge_at(ei, is64, (long long)Ee + e);
        int src = edge_at(ei, is64, e);
        int pos = atomicAdd(&g_cursor[dst], 1);
        g_col[pos] = src;
    }
}

// ---------------- mean aggregation: one warp per node ----------------
__global__ __launch_bounds__(256) void aggregate_kernel(int selIn, const float* __restrict__ x) {
    const float* in = rd_buf(selIn, x);
    int warp = (blockIdx.x * blockDim.x + threadIdx.x) >> 5;
    if (warp >= Nn) return;
    int lane = threadIdx.x & 31;
    int s = g_row_ptr[warp];
    int e = g_row_ptr[warp + 1];
    float4 acc = make_float4(0.f, 0.f, 0.f, 0.f);
    for (int i = s; i < e; i++) {
        int nbr = g_col[i];
        float4 v = *(const float4*)(in + (size_t)nbr * Hh + lane * 4);
        acc.x += v.x; acc.y += v.y; acc.z += v.z; acc.w += v.w;
    }
    float id = g_inv_deg[warp];
    acc.x *= id; acc.y *= id; acc.z *= id; acc.w *= id;
    *(float4*)(g_agg + (size_t)warp * Hh + lane * 4) = acc;
}

// ---------------- tf32 tensor-core dual GEMM (raw fp32 bits -> tf32 truncation) ----
// C = relu(A1@W1 [+ A2@W2] + b), A: [M,128] each, W: [128,128], C: [M,128]
// BM=128, BN=128, BK=16; 256 threads = 8 warps (4 x 2), warp tile 32x64.
__global__ __launch_bounds__(256) void gemm_tf32_kernel(
    int selA1, const float* __restrict__ W1,
    int selA2, const float* __restrict__ W2,
    const float* __restrict__ bias, int selC,
    const float* __restrict__ x, int M)
{
    const float* A1 = rd_buf(selA1, x);
    const float* A2 = (selA2 < 0) ? A1 : rd_buf(selA2, x);
    float* C = wr_buf(selC);

    __shared__ float As[2][128][20];   // [stage][row][k], stride 20 -> conflict-free frags
    __shared__ float Bs[2][16][128];   // [stage][k][n], col XOR-swizzled by (k&3)<<3

    const int t = threadIdx.x;
    const int lane = t & 31;
    const int warp = t >> 5;
    const int g = lane >> 2;       // groupID 0..7
    const int tig = lane & 3;      // threadID_in_group 0..3
    const int warpM = warp & 3;    // 4 warps over M
    const int warpN = warp >> 2;   // 2 warps over N
    const int block_row = blockIdx.x * 128;

    const int nIter = (selA2 >= 0) ? 16 : 8;   // K=256 or K=128 in BK=16 steps

    float acc[2][8][4];
#pragma unroll
    for (int mt = 0; mt < 2; mt++)
#pragma unroll
        for (int nt = 0; nt < 8; nt++)
#pragma unroll
            for (int i = 0; i < 4; i++) acc[mt][nt][i] = 0.f;

    uint32_t asA = (uint32_t)__cvta_generic_to_shared(&As[0][0][0]);
    uint32_t asB = (uint32_t)__cvta_generic_to_shared(&Bs[0][0][0]);

    auto issue = [&](int it, int s) {
        const float* Ap = (it < 8) ? A1 : A2;
        const float* Wp = (it < 8) ? W1 : W2;
        const int kk = (it & 7) * 16;
#pragma unroll
        for (int i = 0; i < 2; i++) {
            int idx = t + i * 256;
            int r = idx >> 2;
            int c4 = (idx & 3) * 4;
            int gr = block_row + r;
            int grc = (gr < M) ? gr : (M - 1);
            const float* src = Ap + (size_t)grc * 128 + kk + c4;
            uint32_t dst = asA + (uint32_t)(((s * 128 + r) * 20 + c4) * 4);
            int sz = (gr < M) ? 16 : 0;
            asm volatile("cp.async.cg.shared.global [%0], [%1], 16, %2;"
                         :: "r"(dst), "l"(src), "r"(sz));
        }
#pragma unroll
        for (int i = 0; i < 2; i++) {
            int idx = t + i * 256;
            int kr = idx >> 5;
            int n = (idx & 31) * 4;
            const float* src = Wp + (size_t)(kk + kr) * 128 + n;
            int pc = n ^ ((kr & 3) << 3);
            uint32_t dst = asB + (uint32_t)(((s * 16 + kr) * 128 + pc) * 4);
            asm volatile("cp.async.cg.shared.global [%0], [%1], 16;"
                         :: "r"(dst), "l"(src));
        }
        asm volatile("cp.async.commit_group;");
    };

    issue(0, 0);

    for (int it = 0; it < nIter; it++) {
        const int s = it & 1;
        if (it + 1 < nIter) {
            issue(it + 1, (it + 1) & 1);
            asm volatile("cp.async.wait_group 1;");
        } else {
            asm volatile("cp.async.wait_group 0;");
        }
        __syncthreads();

#pragma unroll
        for (int ks = 0; ks < 2; ks++) {
            const int kc = ks * 8 + tig;
            // raw fp32 bits fed as tf32 operands (HW truncates low mantissa) — no cvt
            uint32_t af[2][4];
#pragma unroll
            for (int mt = 0; mt < 2; mt++) {
                int rb = warpM * 32 + mt * 16;
                af[mt][0] = __float_as_uint(As[s][rb + g][kc]);
                af[mt][1] = __float_as_uint(As[s][rb + g + 8][kc]);
                af[mt][2] = __float_as_uint(As[s][rb + g][kc + 4]);
                af[mt][3] = __float_as_uint(As[s][rb + g + 8][kc + 4]);
            }
            uint32_t bf[8][2];
            const int sw = (tig & 3) << 3;
#pragma unroll
            for (int nt = 0; nt < 8; nt++) {
                int nb = warpN * 64 + nt * 8 + g;
                bf[nt][0] = __float_as_uint(Bs[s][kc][nb ^ sw]);
                bf[nt][1] = __float_as_uint(Bs[s][kc + 4][nb ^ sw]);
            }
#pragma unroll
            for (int mt = 0; mt < 2; mt++)
#pragma unroll
                for (int nt = 0; nt < 8; nt++) {
                    asm volatile(
                        "mma.sync.aligned.m16n8k8.row.col.f32.tf32.tf32.f32 "
                        "{%0,%1,%2,%3}, {%4,%5,%6,%7}, {%8,%9}, {%0,%1,%2,%3};"
                        : "+f"(acc[mt][nt][0]), "+f"(acc[mt][nt][1]),
                          "+f"(acc[mt][nt][2]), "+f"(acc[mt][nt][3])
                        : "r"(af[mt][0]), "r"(af[mt][1]), "r"(af[mt][2]), "r"(af[mt][3]),
                          "r"(bf[nt][0]), "r"(bf[nt][1]));
                }
        }
        __syncthreads();
    }

    // -------- epilogue: bias + relu, float2 stores --------
#pragma unroll
    for (int mt = 0; mt < 2; mt++) {
        int r0 = block_row + warpM * 32 + mt * 16 + g;
        int r1 = r0 + 8;
#pragma unroll
        for (int nt = 0; nt < 8; nt++) {
            int c0 = warpN * 64 + nt * 8 + 2 * tig;
            float2 bv = *(const float2*)(bias + c0);
            if (r0 < M) {
                float2 o;
                o.x = fmaxf(acc[mt][nt][0] + bv.x, 0.f);
                o.y = fmaxf(acc[mt][nt][1] + bv.y, 0.f);
                *(float2*)(C + (size_t)r0 * 128 + c0) = o;
            }
            if (r1 < M) {
                float2 o;
                o.x = fmaxf(acc[mt][nt][2] + bv.x, 0.f);
                o.y = fmaxf(acc[mt][nt][3] + bv.y, 0.f);
                *(float2*)(C + (size_t)r1 * 128 + c0) = o;
            }
        }
    }
}

// ---------------- fused lin2 + log_softmax: 32 rows per block ----------------
__global__ __launch_bounds__(320) void lin2_logsoftmax_kernel(
    const float* __restrict__ W, const float* __restrict__ b,
    float* __restrict__ outp, int M)
{
    __shared__ float Ws[128 * 40];
    __shared__ float bs[40];
    __shared__ float hs[32][128];
    __shared__ float logits[32][40];
    __shared__ float rmax[32], rlse[32];

    const int t = threadIdx.x;
    for (int i = t; i < 128 * 40; i += 320) Ws[i] = W[i];
    if (t < 40) bs[t] = b[t];

    const int row0 = blockIdx.x * 32;
    for (int i = t; i < 32 * 128; i += 320) {
        int r = i >> 7, c = i & 127;
        int gr = row0 + r;
        hs[r][c] = (gr < M) ? g_h2[(size_t)gr * 128 + c] : 0.f;
    }
    __syncthreads();

    const int j = t % 40;
    const int r0 = t / 40;
    float acc[4];
#pragma unroll
    for (int rr = 0; rr < 4; rr++) acc[rr] = bs[j];
#pragma unroll
    for (int k = 0; k < 128; k++) {
        float w = Ws[k * 40 + j];
#pragma unroll
        for (int rr = 0; rr < 4; rr++)
            acc[rr] += hs[r0 + rr * 8][k] * w;
    }
#pragma unroll
    for (int rr = 0; rr < 4; rr++)
        logits[r0 + rr * 8][j] = acc[rr];
    __syncthreads();

    if (t < 32) {
        float m = -1e30f;
#pragma unroll
        for (int jj = 0; jj < 40; jj++) m = fmaxf(m, logits[t][jj]);
        float s = 0.f;
#pragma unroll
        for (int jj = 0; jj < 40; jj++) s += expf(logits[t][jj] - m);
        rmax[t] = m;
        rlse[t] = logf(s);
    }
    __syncthreads();

#pragma unroll
    for (int rr = 0; rr < 4; rr++) {
        int r = r0 + rr * 8;
        int gr = row0 + r;
        if (gr < M)
            outp[(size_t)gr * 40 + j] = logits[r][j] - rmax[r] - rlse[r];
    }
}

// ---------------- launcher ----------------
extern "C" void kernel_launch(void* const* d_in, const int* in_sizes, int n_in,
                              void* d_out, int out_size) {
    const float* x  = (const float*)d_in[0];
    const void*  ei = d_in[1];
    const float *Wl1 = (const float*)d_in[2],  *bl1 = (const float*)d_in[3],  *Wr1 = (const float*)d_in[4];
    const float *Wl2 = (const float*)d_in[5],  *bl2 = (const float*)d_in[6],  *Wr2 = (const float*)d_in[7];
    const float *Wl3 = (const float*)d_in[8],  *bl3 = (const float*)d_in[9],  *Wr3 = (const float*)d_in[10];
    const float *Wlin1 = (const float*)d_in[11], *blin1 = (const float*)d_in[12];
    const float *Wlin2 = (const float*)d_in[13], *blin2 = (const float*)d_in[14];
    float* outp = (float*)d_out;

    const int TB = 256;
    const int edge_blocks = (Ee + TB - 1) / TB;
    const int node_blocks_1024 = (Nn + 1023) / 1024;
    const int agg_blocks = (Nn * 32 + TB - 1) / TB;
    const int gemm_blocks = (Nn + 127) / 128;
    const int sm_blocks = (Nn + 31) / 32;

    // ---- CSR build ----
    detect_dtype_kernel<<<1, 32>>>(ei);
    zero_deg_kernel<<<node_blocks_1024 * 4, TB>>>();
    count_deg_kernel<<<edge_blocks, TB>>>(ei);
    scan_blocks_kernel<<<node_blocks_1024, 1024>>>();
    scan_sums_kernel<<<1, 32>>>(node_blocks_1024);
    scan_finalize_kernel<<<node_blocks_1024, 1024>>>();
    fill_csr_kernel<<<edge_blocks, TB>>>(ei);

    // selectors: 0 = g_agg, 1 = g_h1, 2 = g_h2, 3 = x
    // ---- layer 1 ----
    aggregate_kernel<<<agg_blocks, TB>>>(3, x);
    gemm_tf32_kernel<<<gemm_blocks, 256>>>(0, Wl1, 3, Wr1, bl1, 1, x, Nn);
    // ---- layer 2 ----
    aggregate_kernel<<<agg_blocks, TB>>>(1, x);
    gemm_tf32_kernel<<<gemm_blocks, 256>>>(0, Wl2, 1, Wr2, bl2, 2, x, Nn);
    // ---- layer 3 ----
    aggregate_kernel<<<agg_blocks, TB>>>(2, x);
    gemm_tf32_kernel<<<gemm_blocks, 256>>>(0, Wl3, 2, Wr3, bl3, 1, x, Nn);
    // ---- lin1 + relu ----
    gemm_tf32_kernel<<<gemm_blocks, 256>>>(1, Wlin1, -1, nullptr, blin1, 2, x, Nn);
    // ---- lin2 + log_softmax ----
    lin2_logsoftmax_kernel<<<sm_blocks, 320>>>(Wlin2, blin2, outp, Nn);
}